// round 8
// baseline (speedup 1.0000x reference)
#include <cuda_runtime.h>
#include <cuda_fp16.h>
#include <cstdint>

// Problem constants
#define M_TOT 16384          // B*T
#define NDIM  512
#define NBH   32             // B*H
#define TSPLIT 32
#define NX  (M_TOT * NDIM)   // 8388608
#define NW1 (NDIM * NDIM)    // 262144

// ---------------- scratch (__device__ globals; no allocation allowed) -------
__device__ float  g_q[M_TOT * NDIM];            // q post-softmax, fp32
__device__ __half g_kh[M_TOT * NDIM];           // k post-softmax, fp16
__device__ __half g_vh[M_TOT * NDIM];           // v, fp16
__device__ __half g_oh[M_TOT * NDIM];           // attn out, fp16
__device__ float  g_ctx[NBH * 64 * 64];
__device__ float  g_ksum[NBH * 64];
__device__ float  g_ctxp[TSPLIT * NBH * 64 * 64];
__device__ float  g_ksump[TSPLIT * NBH * 64];
__device__ __half g_xf[NX];                     // x fp16
__device__ __half g_wf[4 * NW1];                // Wq|Wk|Wv|Wp fp16

// ---------------- helpers ---------------------------------------------------
__device__ __forceinline__ uint32_t smem_u32(const void* p) {
    uint32_t a;
    asm("{ .reg .u64 t; cvta.to.shared.u64 t, %1; cvt.u32.u64 %0, t; }" : "=r"(a) : "l"(p));
    return a;
}
#define SWZ(o) ((o) ^ (((o) >> 3) & 0x70))

__device__ __forceinline__ void cp16(uint32_t dst, const void* src) {
    asm volatile("cp.async.cg.shared.global [%0], [%1], 16;" :: "r"(dst), "l"(src));
}
#define CP_COMMIT() asm volatile("cp.async.commit_group;" ::: "memory")
#define CP_WAIT(n)  asm volatile("cp.async.wait_group %0;" :: "n"(n) : "memory")

#define LDSM4(r, addr) \
    asm volatile("ldmatrix.sync.aligned.m8n8.x4.shared.b16 {%0,%1,%2,%3}, [%4];" \
        : "=r"((r)[0]), "=r"((r)[1]), "=r"((r)[2]), "=r"((r)[3]) : "r"(addr))

#define MMA_F16(d, a, b0, b1) \
    asm volatile("mma.sync.aligned.m16n8k16.row.col.f32.f16.f16.f32 " \
        "{%0,%1,%2,%3}, {%4,%5,%6,%7}, {%8,%9}, {%0,%1,%2,%3};" \
        : "+f"((d)[0]), "+f"((d)[1]), "+f"((d)[2]), "+f"((d)[3]) \
        : "r"((a)[0]), "r"((a)[1]), "r"((a)[2]), "r"((a)[3]), "r"(b0), "r"(b1))

// ---------------------------------------------------------------------------
// HMMA fp16 GEMM v3: CTA tile BM=128, BN=256, BK=64; 8 warps (2m x 4n),
// warp tile 64x64 (8 LDSM : 32 MMA). 3-stage cp.async pipeline, 48KB/stage.
// MODE 0: fused QKV (grid.x=6 over N=1536; slice0 -> q fp32 + softmax,
//         slice1 -> k fp16 + softmax, slice2 -> v fp16 + bias).
// MODE 1: plain fp32 out (grid.x=2).
// ---------------------------------------------------------------------------
#define BKB   128            // bytes per smem row (64 fp16)
#define A_K0B 16384          // 128x64 fp16 A tile
#define B_K0B 32768          // 256x64 fp16 B tile
#define STG   (A_K0B + B_K0B)  // 48KB stage
#define NSTG  3
#define SMEM_GEMM (NSTG * STG)  // 144KB
#define K0STEPS 8

struct GArgs {
    const __half *A, *W;                      // W: base of (multi-)slice weights
    const float *b0, *b1, *b2;                // bias per 512-col slice
    float* qf;                                // slice 0 out (fp32) / plain out
    __half *kh, *vh;                          // slice 1,2 out (fp16)
};

__device__ __forceinline__ void load_k0(
    uint32_t sbase, int stage, int k0, int bm, int bnn, int tid,
    const __half* A, const __half* B)
{
    uint32_t s = sbase + stage * STG;
#pragma unroll
    for (int t = 0; t < 4; t++) {                 // A: 128x64 = 1024 x 16B
        int idx = tid + t * 256;
        int row = idx >> 3, c = idx & 7;
        cp16(s + SWZ((uint32_t)(row * BKB + c * 16)),
             A + (size_t)(bm + row) * 512 + k0 + c * 8);
    }
#pragma unroll
    for (int t = 0; t < 8; t++) {                 // B: 256x64 = 2048 x 16B
        int idx = tid + t * 256;
        int row = idx >> 3, c = idx & 7;
        cp16(s + A_K0B + SWZ((uint32_t)(row * BKB + c * 16)),
             B + (size_t)(bnn + row) * 512 + k0 + c * 8);
    }
}

template <int MODE>
__global__ __launch_bounds__(256, 1) void mma_gemm_k(GArgs args)
{
    extern __shared__ char smem[];
    uint32_t sbase = smem_u32(smem);

    const int tid = threadIdx.x;
    const int lane = tid & 31;
    const int wid = tid >> 5;
    const int wm = (wid & 1) * 64;       // 2 warps in m
    const int wn = (wid >> 1) * 64;      // 4 warps in n
    const int bm = blockIdx.y * 128;
    const int bn = blockIdx.x * 256;
    const int slice = bn >> 9;           // 512-col slice index
    const int bnn = bn & 511;            // col offset within slice (0 or 256)

    const __half* W = args.W + (size_t)slice * NW1;
    const float* bias = (slice == 0) ? args.b0 : (slice == 1) ? args.b1 : args.b2;
    const bool do_sm = (MODE == 0) && (slice < 2);

    float acc[4][8][4];
#pragma unroll
    for (int i = 0; i < 4; i++)
#pragma unroll
        for (int j = 0; j < 8; j++)
#pragma unroll
            for (int p = 0; p < 4; p++) acc[i][j][p] = 0.f;

    const int a_row = wm + (lane & 15);
    const int a_cb  = (lane >> 4) * 16;
    const int b_row = wn + (lane & 7) + ((lane >> 4) & 1) * 8;
    const int b_cb  = ((lane >> 3) & 1) * 16;

    load_k0(sbase, 0, 0, bm, bnn, tid, args.A, W);
    CP_COMMIT();
    load_k0(sbase, 1, 64, bm, bnn, tid, args.A, W);
    CP_COMMIT();

    for (int i = 0; i < K0STEPS; i++) {
        CP_WAIT(1);
        __syncthreads();
        if (i + 2 < K0STEPS)
            load_k0(sbase, (i + 2) % NSTG, (i + 2) * 64, bm, bnn, tid, args.A, W);
        CP_COMMIT();

        uint32_t sA = sbase + (i % NSTG) * STG;
        uint32_t sB = sA + A_K0B;
#pragma unroll
        for (int ks = 0; ks < 4; ks++) {
            uint32_t a[4][4], b[4][4];
#pragma unroll
            for (int mi = 0; mi < 4; mi++)
                LDSM4(a[mi], sA + SWZ((uint32_t)((a_row + mi * 16) * BKB + ks * 32 + a_cb)));
#pragma unroll
            for (int nb = 0; nb < 4; nb++)
                LDSM4(b[nb], sB + SWZ((uint32_t)((b_row + nb * 16) * BKB + ks * 32 + b_cb)));
#pragma unroll
            for (int mi = 0; mi < 4; mi++)
#pragma unroll
                for (int nb = 0; nb < 4; nb++) {
                    MMA_F16(acc[mi][nb * 2 + 0], a[mi], b[nb][0], b[nb][1]);
                    MMA_F16(acc[mi][nb * 2 + 1], a[mi], b[nb][2], b[nb][3]);
                }
        }
    }

    // ---- epilogue: bias, optional softmax, store --------------------------
#pragma unroll
    for (int nf = 0; nf < 8; nf++) {
        int col = bnn + wn + (lane & 3) * 2 + nf * 8;
        float bb0 = __ldg(bias + col);
        float bb1 = __ldg(bias + col + 1);
#pragma unroll
        for (int mi = 0; mi < 4; mi++) {
            acc[mi][nf][0] += bb0; acc[mi][nf][1] += bb1;
            acc[mi][nf][2] += bb0; acc[mi][nf][3] += bb1;
        }
    }

    if (do_sm) {
        // per-row softmax over the warp's 64 cols (row = lane quad)
#pragma unroll
        for (int mi = 0; mi < 4; mi++)
#pragma unroll
            for (int half = 0; half < 2; half++) {
                float m = -1e30f;
#pragma unroll
                for (int nf = 0; nf < 8; nf++)
                    m = fmaxf(m, fmaxf(acc[mi][nf][half * 2], acc[mi][nf][half * 2 + 1]));
                m = fmaxf(m, __shfl_xor_sync(0xffffffffu, m, 1));
                m = fmaxf(m, __shfl_xor_sync(0xffffffffu, m, 2));
                float s = 0.f;
#pragma unroll
                for (int nf = 0; nf < 8; nf++) {
                    float e0 = __expf(acc[mi][nf][half * 2] - m);
                    float e1 = __expf(acc[mi][nf][half * 2 + 1] - m);
                    acc[mi][nf][half * 2] = e0;
                    acc[mi][nf][half * 2 + 1] = e1;
                    s += e0 + e1;
                }
                s += __shfl_xor_sync(0xffffffffu, s, 1);
                s += __shfl_xor_sync(0xffffffffu, s, 2);
                float inv = 1.f / s;
#pragma unroll
                for (int nf = 0; nf < 8; nf++) {
                    acc[mi][nf][half * 2] *= inv;
                    acc[mi][nf][half * 2 + 1] *= inv;
                }
            }
    }

    const int r0 = bm + wm + (lane >> 2);
    const int c0 = bnn + wn + (lane & 3) * 2;

    if (MODE == 1 || slice == 0) {
        float* out = args.qf;
#pragma unroll
        for (int nf = 0; nf < 8; nf++) {
            int col = c0 + nf * 8;
#pragma unroll
            for (int mi = 0; mi < 4; mi++) {
                int row = r0 + mi * 16;
                float2 v0 = {acc[mi][nf][0], acc[mi][nf][1]};
                float2 v1 = {acc[mi][nf][2], acc[mi][nf][3]};
                *(float2*)(out + (size_t)row * 512 + col) = v0;
                *(float2*)(out + (size_t)(row + 8) * 512 + col) = v1;
            }
        }
    } else {
        __half* out = (slice == 1) ? args.kh : args.vh;
#pragma unroll
        for (int nf = 0; nf < 8; nf++) {
            int col = c0 + nf * 8;
#pragma unroll
            for (int mi = 0; mi < 4; mi++) {
                int row = r0 + mi * 16;
                __half2 v0 = __floats2half2_rn(acc[mi][nf][0], acc[mi][nf][1]);
                __half2 v1 = __floats2half2_rn(acc[mi][nf][2], acc[mi][nf][3]);
                *(__half2*)(out + (size_t)row * 512 + col) = v0;
                *(__half2*)(out + (size_t)(row + 8) * 512 + col) = v1;
            }
        }
    }
}

// ---------------------------------------------------------------------------
// fused fp32 -> fp16 conversion: x + all four weights
// ---------------------------------------------------------------------------
__global__ __launch_bounds__(256) void conv_all_k(
    const float* __restrict__ x,
    const float* __restrict__ Wq, const float* __restrict__ Wk,
    const float* __restrict__ Wv, const float* __restrict__ Wp,
    __half* __restrict__ xf, __half* __restrict__ wf)
{
    int i = (blockIdx.x * 256 + threadIdx.x) * 4;
    const float* src;
    __half* dst;
    int o;
    if (i < NX) { src = x; dst = xf; o = i; }
    else {
        int j = i - NX;
        int w = j >> 18;                  // NW1 = 2^18
        o = j & (NW1 - 1);
        src = (w == 0) ? Wq : (w == 1) ? Wk : (w == 2) ? Wv : Wp;
        dst = wf + ((size_t)w << 18);
    }
    float4 v = *(const float4*)(src + o);
    *(__half2*)(dst + o)     = __floats2half2_rn(v.x, v.y);
    *(__half2*)(dst + o + 2) = __floats2half2_rn(v.z, v.w);
}

// ---------------------------------------------------------------------------
// context partials + k_sum partials; k,v read as fp16
// ---------------------------------------------------------------------------
__global__ __launch_bounds__(256) void ctx_partial_k(
    const __half* __restrict__ K, const __half* __restrict__ V,
    float* __restrict__ ctxp, float* __restrict__ ksump)
{
    __shared__ float ks[32][65];
    __shared__ float vs[32][65];
    const int bh = blockIdx.x, b = bh >> 3, h = bh & 7;
    const int ts = blockIdx.y, tid = threadIdx.x;
    const int tx = tid & 15, ty = tid >> 4;
    const int col = tid & 63, trow = tid >> 6;

    float acc[4][4];
#pragma unroll
    for (int i = 0; i < 4; i++)
#pragma unroll
        for (int j = 0; j < 4; j++) acc[i][j] = 0.f;
    float ksacc[4] = {0.f, 0.f, 0.f, 0.f};
    const int rowbase = b * 4096 + ts * 128;

    for (int tt = 0; tt < 128; tt += 32) {
#pragma unroll
        for (int p = 0; p < 8; p++) {
            int t = trow + p * 4;
            size_t g = (size_t)(rowbase + tt + t) * 512 + h * 64 + col;
            ks[t][col] = __half2float(K[g]);
            vs[t][col] = __half2float(V[g]);
        }
        __syncthreads();
#pragma unroll
        for (int t = 0; t < 32; t++) {
            float a[4], bb[4];
#pragma unroll
            for (int i = 0; i < 4; i++) a[i] = ks[t][ty * 4 + i];
#pragma unroll
            for (int j = 0; j < 4; j++) bb[j] = vs[t][tx * 4 + j];
#pragma unroll
            for (int i = 0; i < 4; i++)
#pragma unroll
                for (int j = 0; j < 4; j++) acc[i][j] += a[i] * bb[j];
            if (tx == 0)
#pragma unroll
                for (int i = 0; i < 4; i++) ksacc[i] += a[i];
        }
        __syncthreads();
    }
    float* cp = ctxp + (size_t)(ts * NBH + bh) * 4096;
#pragma unroll
    for (int i = 0; i < 4; i++)
#pragma unroll
        for (int j = 0; j < 4; j++)
            cp[(ty * 4 + i) * 64 + tx * 4 + j] = acc[i][j];
    if (tx == 0)
#pragma unroll
        for (int i = 0; i < 4; i++)
            ksump[(size_t)(ts * NBH + bh) * 64 + ty * 4 + i] = ksacc[i];
}

// combined reduce: ctx (NBH*4096) then ksum (NBH*64)
__global__ void reduce_all_k(const float* __restrict__ ctxp,
                             const float* __restrict__ ksump,
                             float* __restrict__ ctx, float* __restrict__ ksum)
{
    int i = blockIdx.x * blockDim.x + threadIdx.x;
    if (i < NBH * 4096) {
        float s = 0.f;
#pragma unroll
        for (int p = 0; p < TSPLIT; p++) s += ctxp[(size_t)p * NBH * 4096 + i];
        ctx[i] = s;
    } else {
        int j = i - NBH * 4096;
        if (j < NBH * 64) {
            float s = 0.f;
#pragma unroll
            for (int p = 0; p < TSPLIT; p++) s += ksump[(size_t)p * NBH * 64 + j];
            ksum[j] = s;
        }
    }
}

// ---------------------------------------------------------------------------
// out = (q @ ctx) * Dinv + q  -> fp16 o for final GEMM. q read fp32.
// ---------------------------------------------------------------------------
__global__ __launch_bounds__(256) void attn_out_k(
    const float* __restrict__ Q, const float* __restrict__ ctx,
    const float* __restrict__ ksum, __half* __restrict__ Oh)
{
    __shared__ float cs[64][64];
    __shared__ float qs[64][65];
    __shared__ float kss[64];
    const int bh = blockIdx.x, b = bh >> 3, h = bh & 7;
    const int tb = blockIdx.y, tid = threadIdx.x;

    const float* cg = ctx + (size_t)bh * 4096;
    for (int i = tid; i < 4096; i += 256) cs[i >> 6][i & 63] = cg[i];
    if (tid < 64) kss[tid] = ksum[bh * 64 + tid];

    const int rowbase = b * 4096 + tb * 64;
    const int col = tid & 63, rr = tid >> 6;
#pragma unroll
    for (int p = 0; p < 16; p++) {
        int r = rr + p * 4;
        qs[r][col] = Q[(size_t)(rowbase + r) * 512 + h * 64 + col];
    }
    __syncthreads();

    const int r = tid >> 2, e0 = (tid & 3) * 16;
    float acc[16];
#pragma unroll
    for (int j = 0; j < 16; j++) acc[j] = 0.f;
    float dv = 0.f;
#pragma unroll
    for (int d = 0; d < 64; d++) {
        float qv = qs[r][d];
        dv += qv * kss[d];
#pragma unroll
        for (int j = 0; j < 16; j++) acc[j] += qv * cs[d][e0 + j];
    }
    float Dinv = 1.f / dv;
    size_t base = (size_t)(rowbase + r) * 512 + h * 64 + e0;
#pragma unroll
    for (int j = 0; j < 16; j += 2) {
        float v0 = acc[j] * Dinv + qs[r][e0 + j];
        float v1 = acc[j + 1] * Dinv + qs[r][e0 + j + 1];
        *(__half2*)(Oh + base + j) = __floats2half2_rn(v0, v1);
    }
}

// ---------------------------------------------------------------------------
extern "C" void kernel_launch(void* const* d_in, const int* in_sizes, int n_in,
                              void* d_out, int out_size)
{
    const float* x  = (const float*)d_in[0];
    const float* Wq = (const float*)d_in[1];
    const float* bq = (const float*)d_in[2];
    const float* Wk = (const float*)d_in[3];
    const float* bk = (const float*)d_in[4];
    const float* Wv = (const float*)d_in[5];
    const float* bv = (const float*)d_in[6];
    const float* Wp = (const float*)d_in[7];
    const float* bp = (const float*)d_in[8];
    float* out = (float*)d_out;

    float *q, *ctx, *ksum, *ctxp, *ksump;
    __half *kh, *vh, *oh, *xf, *wf;
    cudaGetSymbolAddress((void**)&q, g_q);
    cudaGetSymbolAddress((void**)&kh, g_kh);
    cudaGetSymbolAddress((void**)&vh, g_vh);
    cudaGetSymbolAddress((void**)&oh, g_oh);
    cudaGetSymbolAddress((void**)&ctx, g_ctx);
    cudaGetSymbolAddress((void**)&ksum, g_ksum);
    cudaGetSymbolAddress((void**)&ctxp, g_ctxp);
    cudaGetSymbolAddress((void**)&ksump, g_ksump);
    cudaGetSymbolAddress((void**)&xf, g_xf);
    cudaGetSymbolAddress((void**)&wf, g_wf);

    cudaFuncSetAttribute(mma_gemm_k<0>, cudaFuncAttributeMaxDynamicSharedMemorySize,
                         SMEM_GEMM);
    cudaFuncSetAttribute(mma_gemm_k<1>, cudaFuncAttributeMaxDynamicSharedMemorySize,
                         SMEM_GEMM);

    // fp32 -> fp16 conversions (x + all weights, one launch)
    conv_all_k<<<(NX + 4 * NW1) / 4 / 256, 256>>>(x, Wq, Wk, Wv, Wp, xf, wf);

    // fused QKV GEMM + softmax epilogue
    GArgs aqkv{xf, wf, bq, bk, bv, q, kh, vh};
    mma_gemm_k<0><<<dim3(6, 128), 256, SMEM_GEMM>>>(aqkv);

    ctx_partial_k<<<dim3(NBH, TSPLIT), 256>>>(kh, vh, ctxp, ksump);
    reduce_all_k<<<(NBH * 4096 + NBH * 64 + 255) / 256, 256>>>(ctxp, ksump, ctx, ksum);

    attn_out_k<<<dim3(NBH, 64), 256>>>(q, ctx, ksum, oh);

    // output projection (plain fp32 out)
    GArgs ap{oh, wf + 3 * NW1, bp, bp, bp, out, nullptr, nullptr};
    mma_gemm_k<1><<<dim3(2, 128), 256, SMEM_GEMM>>>(ap);
}

// round 9
// speedup vs baseline: 1.0750x; 1.0750x over previous
#include <cuda_runtime.h>
#include <cuda_fp16.h>
#include <cstdint>

// Problem constants
#define M_TOT 16384          // B*T
#define NDIM  512
#define NBH   32             // B*H
#define TSPLIT 16
#define NX  (M_TOT * NDIM)   // 8388608
#define NW1 (NDIM * NDIM)    // 262144

// ---------------- scratch (__device__ globals; no allocation allowed) -------
__device__ float  g_q[M_TOT * NDIM];            // q post-softmax, fp32
__device__ __half g_kh[M_TOT * NDIM];           // k post-softmax, fp16
__device__ __half g_vh[M_TOT * NDIM];           // v, fp16
__device__ __half g_oh[M_TOT * NDIM];           // attn out, fp16
__device__ float  g_ctx[NBH * 64 * 64];
__device__ float  g_ksum[NBH * 64];
__device__ float  g_ctxp[TSPLIT * NBH * 64 * 64];
__device__ float  g_ksump[TSPLIT * NBH * 64];
__device__ __half g_xf[NX];                     // x fp16
__device__ __half g_wf[4 * NW1];                // Wq|Wk|Wv|Wp fp16

// ---------------- helpers ---------------------------------------------------
__device__ __forceinline__ uint32_t smem_u32(const void* p) {
    uint32_t a;
    asm("{ .reg .u64 t; cvta.to.shared.u64 t, %1; cvt.u32.u64 %0, t; }" : "=r"(a) : "l"(p));
    return a;
}
#define SWZ(o) ((o) ^ (((o) >> 3) & 0x70))

__device__ __forceinline__ void cp16(uint32_t dst, const void* src) {
    asm volatile("cp.async.cg.shared.global [%0], [%1], 16;" :: "r"(dst), "l"(src));
}
#define CP_COMMIT() asm volatile("cp.async.commit_group;" ::: "memory")
#define CP_WAIT(n)  asm volatile("cp.async.wait_group %0;" :: "n"(n) : "memory")

#define LDSM4(r, addr) \
    asm volatile("ldmatrix.sync.aligned.m8n8.x4.shared.b16 {%0,%1,%2,%3}, [%4];" \
        : "=r"((r)[0]), "=r"((r)[1]), "=r"((r)[2]), "=r"((r)[3]) : "r"(addr))

#define MMA_F16(d, a, b0, b1) \
    asm volatile("mma.sync.aligned.m16n8k16.row.col.f32.f16.f16.f32 " \
        "{%0,%1,%2,%3}, {%4,%5,%6,%7}, {%8,%9}, {%0,%1,%2,%3};" \
        : "+f"((d)[0]), "+f"((d)[1]), "+f"((d)[2]), "+f"((d)[3]) \
        : "r"((a)[0]), "r"((a)[1]), "r"((a)[2]), "r"((a)[3]), "r"(b0), "r"(b1))

// ---------------------------------------------------------------------------
// HMMA fp16 GEMM (R6 config): CTA tile BM=128, BN=128, BK=64; 8 warps
// (4m x 2n), warp tile 32x64. 3-stage cp.async pipeline (32KB/stage), occ 2.
// MODE 0: fused QKV (grid.x=12; slice0 -> q fp32 + softmax, slice1 -> k fp16 +
//         softmax, slice2 -> v fp16 + bias). MODE 1: plain fp32 out (grid.x=4).
// ---------------------------------------------------------------------------
#define BKB   128            // bytes per smem row (64 fp16)
#define K0B   16384          // one 128x64 fp16 tile
#define STG   (2 * K0B)      // 32KB stage: A | B
#define NSTG  3
#define SMEM_GEMM (NSTG * STG)
#define K0STEPS 8

struct GArgs {
    const __half *A, *W;                      // W: base of (multi-)slice weights
    const float *b0, *b1, *b2;                // bias per 512-col slice
    float* qf;                                // slice 0 out (fp32) / plain out
    __half *kh, *vh;                          // slice 1,2 out (fp16)
};

__device__ __forceinline__ void load_k0(
    uint32_t sbase, int stage, int k0, int bm, int bnn, int tid,
    const __half* A, const __half* B)
{
    uint32_t s = sbase + stage * STG;
#pragma unroll
    for (int t = 0; t < 4; t++) {
        int idx = tid + t * 256;                  // 1024 x 16B per tile
        int row = idx >> 3, c = idx & 7;
        uint32_t off = SWZ((uint32_t)(row * BKB + c * 16));
        cp16(s + off,       A + (size_t)(bm + row) * 512 + k0 + c * 8);
        cp16(s + K0B + off, B + (size_t)(bnn + row) * 512 + k0 + c * 8);
    }
}

template <int MODE>
__global__ __launch_bounds__(256, 2) void mma_gemm_k(GArgs args)
{
    extern __shared__ char smem[];
    uint32_t sbase = smem_u32(smem);

    const int tid = threadIdx.x;
    const int lane = tid & 31;
    const int wid = tid >> 5;
    const int wm = (wid & 3) * 32;
    const int wn = (wid >> 2) * 64;
    const int bm = blockIdx.y * 128;
    const int bn = blockIdx.x * 128;
    const int slice = bn >> 9;
    const int bnn = bn & 511;

    const __half* W = args.W + (size_t)slice * NW1;
    const float* bias = (slice == 0) ? args.b0 : (slice == 1) ? args.b1 : args.b2;
    const bool do_sm = (MODE == 0) && (slice < 2);

    float acc[2][8][4];
#pragma unroll
    for (int i = 0; i < 2; i++)
#pragma unroll
        for (int j = 0; j < 8; j++)
#pragma unroll
            for (int p = 0; p < 4; p++) acc[i][j][p] = 0.f;

    const int a_row = wm + (lane & 15);
    const int a_cb  = (lane >> 4) * 16;
    const int b_row = wn + (lane & 7) + ((lane >> 4) & 1) * 8;
    const int b_cb  = ((lane >> 3) & 1) * 16;

    load_k0(sbase, 0, 0, bm, bnn, tid, args.A, W);
    CP_COMMIT();
    load_k0(sbase, 1, 64, bm, bnn, tid, args.A, W);
    CP_COMMIT();

    for (int i = 0; i < K0STEPS; i++) {
        CP_WAIT(1);
        __syncthreads();
        if (i + 2 < K0STEPS)
            load_k0(sbase, (i + 2) % NSTG, (i + 2) * 64, bm, bnn, tid, args.A, W);
        CP_COMMIT();

        uint32_t sA = sbase + (i % NSTG) * STG;
        uint32_t sB = sA + K0B;
#pragma unroll
        for (int ks = 0; ks < 4; ks++) {
            uint32_t a[2][4], b[4][4];
#pragma unroll
            for (int mi = 0; mi < 2; mi++)
                LDSM4(a[mi], sA + SWZ((uint32_t)((a_row + mi * 16) * BKB + ks * 32 + a_cb)));
#pragma unroll
            for (int nb = 0; nb < 4; nb++)
                LDSM4(b[nb], sB + SWZ((uint32_t)((b_row + nb * 16) * BKB + ks * 32 + b_cb)));
#pragma unroll
            for (int mi = 0; mi < 2; mi++)
#pragma unroll
                for (int nb = 0; nb < 4; nb++) {
                    MMA_F16(acc[mi][nb * 2 + 0], a[mi], b[nb][0], b[nb][1]);
                    MMA_F16(acc[mi][nb * 2 + 1], a[mi], b[nb][2], b[nb][3]);
                }
        }
    }

    // ---- epilogue: bias, optional softmax, store --------------------------
#pragma unroll
    for (int nf = 0; nf < 8; nf++) {
        int col = bnn + wn + (lane & 3) * 2 + nf * 8;
        float bb0 = __ldg(bias + col);
        float bb1 = __ldg(bias + col + 1);
#pragma unroll
        for (int mi = 0; mi < 2; mi++) {
            acc[mi][nf][0] += bb0; acc[mi][nf][1] += bb1;
            acc[mi][nf][2] += bb0; acc[mi][nf][3] += bb1;
        }
    }

    if (do_sm) {
        // per-row softmax over the warp's 64 cols (row = lane quad)
#pragma unroll
        for (int mi = 0; mi < 2; mi++)
#pragma unroll
            for (int half = 0; half < 2; half++) {
                float m = -1e30f;
#pragma unroll
                for (int nf = 0; nf < 8; nf++)
                    m = fmaxf(m, fmaxf(acc[mi][nf][half * 2], acc[mi][nf][half * 2 + 1]));
                m = fmaxf(m, __shfl_xor_sync(0xffffffffu, m, 1));
                m = fmaxf(m, __shfl_xor_sync(0xffffffffu, m, 2));
                float s = 0.f;
#pragma unroll
                for (int nf = 0; nf < 8; nf++) {
                    float e0 = __expf(acc[mi][nf][half * 2] - m);
                    float e1 = __expf(acc[mi][nf][half * 2 + 1] - m);
                    acc[mi][nf][half * 2] = e0;
                    acc[mi][nf][half * 2 + 1] = e1;
                    s += e0 + e1;
                }
                s += __shfl_xor_sync(0xffffffffu, s, 1);
                s += __shfl_xor_sync(0xffffffffu, s, 2);
                float inv = 1.f / s;
#pragma unroll
                for (int nf = 0; nf < 8; nf++) {
                    acc[mi][nf][half * 2] *= inv;
                    acc[mi][nf][half * 2 + 1] *= inv;
                }
            }
    }

    const int r0 = bm + wm + (lane >> 2);
    const int c0 = bnn + wn + (lane & 3) * 2;

    if (MODE == 1 || slice == 0) {
        float* out = args.qf;
#pragma unroll
        for (int nf = 0; nf < 8; nf++) {
            int col = c0 + nf * 8;
#pragma unroll
            for (int mi = 0; mi < 2; mi++) {
                int row = r0 + mi * 16;
                float2 v0 = {acc[mi][nf][0], acc[mi][nf][1]};
                float2 v1 = {acc[mi][nf][2], acc[mi][nf][3]};
                *(float2*)(out + (size_t)row * 512 + col) = v0;
                *(float2*)(out + (size_t)(row + 8) * 512 + col) = v1;
            }
        }
    } else {
        __half* out = (slice == 1) ? args.kh : args.vh;
#pragma unroll
        for (int nf = 0; nf < 8; nf++) {
            int col = c0 + nf * 8;
#pragma unroll
            for (int mi = 0; mi < 2; mi++) {
                int row = r0 + mi * 16;
                __half2 v0 = __floats2half2_rn(acc[mi][nf][0], acc[mi][nf][1]);
                __half2 v1 = __floats2half2_rn(acc[mi][nf][2], acc[mi][nf][3]);
                *(__half2*)(out + (size_t)row * 512 + col) = v0;
                *(__half2*)(out + (size_t)(row + 8) * 512 + col) = v1;
            }
        }
    }
}

// ---------------------------------------------------------------------------
// fused fp32 -> fp16 conversion: x + all four weights
// ---------------------------------------------------------------------------
__global__ __launch_bounds__(256) void conv_all_k(
    const float* __restrict__ x,
    const float* __restrict__ Wq, const float* __restrict__ Wk,
    const float* __restrict__ Wv, const float* __restrict__ Wp,
    __half* __restrict__ xf, __half* __restrict__ wf)
{
    int i = (blockIdx.x * 256 + threadIdx.x) * 4;
    const float* src;
    __half* dst;
    int o;
    if (i < NX) { src = x; dst = xf; o = i; }
    else {
        int j = i - NX;
        int w = j >> 18;                  // NW1 = 2^18
        o = j & (NW1 - 1);
        src = (w == 0) ? Wq : (w == 1) ? Wk : (w == 2) ? Wv : Wp;
        dst = wf + ((size_t)w << 18);
    }
    float4 v = *(const float4*)(src + o);
    *(__half2*)(dst + o)     = __floats2half2_rn(v.x, v.y);
    *(__half2*)(dst + o + 2) = __floats2half2_rn(v.z, v.w);
}

// ---------------------------------------------------------------------------
// context partials + k_sum partials; k,v fp16, T slice of 256 per block.
// Smem rows padded to 68 floats (16B-divisible) -> LDS.128 inner reads.
// ---------------------------------------------------------------------------
__global__ __launch_bounds__(256) void ctx_partial_k(
    const __half* __restrict__ K, const __half* __restrict__ V,
    float* __restrict__ ctxp, float* __restrict__ ksump)
{
    __shared__ float ks[32][68];
    __shared__ float vs[32][68];
    const int bh = blockIdx.x, b = bh >> 3, h = bh & 7;
    const int ts = blockIdx.y, tid = threadIdx.x;
    const int tx = tid & 15, ty = tid >> 4;
    const int col2 = (tid & 31) * 2;       // half2 column pair
    const int trow = tid >> 5;             // 8 t-rows per pass

    float acc[4][4];
#pragma unroll
    for (int i = 0; i < 4; i++)
#pragma unroll
        for (int j = 0; j < 4; j++) acc[i][j] = 0.f;
    float ksacc[4] = {0.f, 0.f, 0.f, 0.f};
    const int rowbase = b * 4096 + ts * 256;

    for (int tt = 0; tt < 256; tt += 32) {
#pragma unroll
        for (int p = 0; p < 4; p++) {
            int t = trow + p * 8;
            size_t g = (size_t)(rowbase + tt + t) * 512 + h * 64 + col2;
            float2 kf = __half22float2(*(const __half2*)(K + g));
            float2 vf = __half22float2(*(const __half2*)(V + g));
            ks[t][col2] = kf.x; ks[t][col2 + 1] = kf.y;
            vs[t][col2] = vf.x; vs[t][col2 + 1] = vf.y;
        }
        __syncthreads();
#pragma unroll
        for (int t = 0; t < 32; t++) {
            float4 af = *(const float4*)(&ks[t][ty * 4]);
            float4 bf = *(const float4*)(&vs[t][tx * 4]);
            float a[4] = {af.x, af.y, af.z, af.w};
            float bb[4] = {bf.x, bf.y, bf.z, bf.w};
#pragma unroll
            for (int i = 0; i < 4; i++)
#pragma unroll
                for (int j = 0; j < 4; j++) acc[i][j] += a[i] * bb[j];
            if (tx == 0)
#pragma unroll
                for (int i = 0; i < 4; i++) ksacc[i] += a[i];
        }
        __syncthreads();
    }
    float* cp = ctxp + (size_t)(ts * NBH + bh) * 4096;
#pragma unroll
    for (int i = 0; i < 4; i++)
#pragma unroll
        for (int j = 0; j < 4; j++)
            cp[(ty * 4 + i) * 64 + tx * 4 + j] = acc[i][j];
    if (tx == 0)
#pragma unroll
        for (int i = 0; i < 4; i++)
            ksump[(size_t)(ts * NBH + bh) * 64 + ty * 4 + i] = ksacc[i];
}

// combined reduce: ctx (NBH*4096) then ksum (NBH*64)
__global__ void reduce_all_k(const float* __restrict__ ctxp,
                             const float* __restrict__ ksump,
                             float* __restrict__ ctx, float* __restrict__ ksum)
{
    int i = blockIdx.x * blockDim.x + threadIdx.x;
    if (i < NBH * 4096) {
        float s = 0.f;
#pragma unroll
        for (int p = 0; p < TSPLIT; p++) s += ctxp[(size_t)p * NBH * 4096 + i];
        ctx[i] = s;
    } else {
        int j = i - NBH * 4096;
        if (j < NBH * 64) {
            float s = 0.f;
#pragma unroll
            for (int p = 0; p < TSPLIT; p++) s += ksump[(size_t)p * NBH * 64 + j];
            ksum[j] = s;
        }
    }
}

// ---------------------------------------------------------------------------
// out = (q @ ctx) * Dinv + q  -> fp16 o for final GEMM. q read fp32.
// ---------------------------------------------------------------------------
__global__ __launch_bounds__(256) void attn_out_k(
    const float* __restrict__ Q, const float* __restrict__ ctx,
    const float* __restrict__ ksum, __half* __restrict__ Oh)
{
    __shared__ float cs[64][64];
    __shared__ float qs[64][68];
    __shared__ float kss[64];
    const int bh = blockIdx.x, b = bh >> 3, h = bh & 7;
    const int tb = blockIdx.y, tid = threadIdx.x;

    const float* cg = ctx + (size_t)bh * 4096;
    for (int i = tid; i < 4096; i += 256) cs[i >> 6][i & 63] = cg[i];
    if (tid < 64) kss[tid] = ksum[bh * 64 + tid];

    const int rowbase = b * 4096 + tb * 64;
    const int col = tid & 63, rr = tid >> 6;
#pragma unroll
    for (int p = 0; p < 16; p++) {
        int r = rr + p * 4;
        qs[r][col] = Q[(size_t)(rowbase + r) * 512 + h * 64 + col];
    }
    __syncthreads();

    const int r = tid >> 2, e0 = (tid & 3) * 16;
    float acc[16];
#pragma unroll
    for (int j = 0; j < 16; j++) acc[j] = 0.f;
    float dv = 0.f;
#pragma unroll
    for (int d = 0; d < 64; d++) {
        float qv = qs[r][d];
        dv += qv * kss[d];
#pragma unroll
        for (int j = 0; j < 16; j++) acc[j] += qv * cs[d][e0 + j];
    }
    float Dinv = 1.f / dv;
    size_t base = (size_t)(rowbase + r) * 512 + h * 64 + e0;
#pragma unroll
    for (int j = 0; j < 16; j += 2) {
        float v0 = acc[j] * Dinv + qs[r][e0 + j];
        float v1 = acc[j + 1] * Dinv + qs[r][e0 + j + 1];
        *(__half2*)(Oh + base + j) = __floats2half2_rn(v0, v1);
    }
}

// ---------------------------------------------------------------------------
extern "C" void kernel_launch(void* const* d_in, const int* in_sizes, int n_in,
                              void* d_out, int out_size)
{
    const float* x  = (const float*)d_in[0];
    const float* Wq = (const float*)d_in[1];
    const float* bq = (const float*)d_in[2];
    const float* Wk = (const float*)d_in[3];
    const float* bk = (const float*)d_in[4];
    const float* Wv = (const float*)d_in[5];
    const float* bv = (const float*)d_in[6];
    const float* Wp = (const float*)d_in[7];
    const float* bp = (const float*)d_in[8];
    float* out = (float*)d_out;

    float *q, *ctx, *ksum, *ctxp, *ksump;
    __half *kh, *vh, *oh, *xf, *wf;
    cudaGetSymbolAddress((void**)&q, g_q);
    cudaGetSymbolAddress((void**)&kh, g_kh);
    cudaGetSymbolAddress((void**)&vh, g_vh);
    cudaGetSymbolAddress((void**)&oh, g_oh);
    cudaGetSymbolAddress((void**)&ctx, g_ctx);
    cudaGetSymbolAddress((void**)&ksum, g_ksum);
    cudaGetSymbolAddress((void**)&ctxp, g_ctxp);
    cudaGetSymbolAddress((void**)&ksump, g_ksump);
    cudaGetSymbolAddress((void**)&xf, g_xf);
    cudaGetSymbolAddress((void**)&wf, g_wf);

    cudaFuncSetAttribute(mma_gemm_k<0>, cudaFuncAttributeMaxDynamicSharedMemorySize,
                         SMEM_GEMM);
    cudaFuncSetAttribute(mma_gemm_k<1>, cudaFuncAttributeMaxDynamicSharedMemorySize,
                         SMEM_GEMM);

    // fp32 -> fp16 conversions (x + all weights, one launch)
    conv_all_k<<<(NX + 4 * NW1) / 4 / 256, 256>>>(x, Wq, Wk, Wv, Wp, xf, wf);

    // fused QKV GEMM + softmax epilogue
    GArgs aqkv{xf, wf, bq, bk, bv, q, kh, vh};
    mma_gemm_k<0><<<dim3(12, 128), 256, SMEM_GEMM>>>(aqkv);

    ctx_partial_k<<<dim3(NBH, TSPLIT), 256>>>(kh, vh, ctxp, ksump);
    reduce_all_k<<<(NBH * 4096 + NBH * 64 + 255) / 256, 256>>>(ctxp, ksump, ctx, ksum);

    attn_out_k<<<dim3(NBH, 64), 256>>>(q, ctx, ksum, oh);

    // output projection (plain fp32 out)
    GArgs ap{oh, wf + 3 * NW1, bp, bp, bp, out, nullptr, nullptr};
    mma_gemm_k<1><<<dim3(4, 128), 256, SMEM_GEMM>>>(ap);
}

// round 10
// speedup vs baseline: 1.0912x; 1.0150x over previous
#include <cuda_runtime.h>
#include <cuda_fp16.h>
#include <cstdint>

// Problem constants
#define M_TOT 16384          // B*T
#define NDIM  512
#define NBH   32             // B*H
#define TSPLIT 16
#define NX  (M_TOT * NDIM)   // 8388608
#define NW1 (NDIM * NDIM)    // 262144

// ---------------- scratch (__device__ globals; no allocation allowed) -------
__device__ float  g_q[M_TOT * NDIM];            // q post-softmax, fp32
__device__ __half g_kh[M_TOT * NDIM];           // k post-softmax, fp16
__device__ __half g_vh[M_TOT * NDIM];           // v, fp16
__device__ __half g_oh[M_TOT * NDIM];           // attn out, fp16
__device__ float  g_ctx[NBH * 64 * 64];
__device__ float  g_ksum[NBH * 64];
__device__ float  g_ctxp[TSPLIT * NBH * 64 * 64];
__device__ float  g_ksump[TSPLIT * NBH * 64];
__device__ __half g_xf[NX];                     // x fp16
__device__ __half g_wf[4 * NW1];                // Wq|Wk|Wv|Wp fp16

// ---------------- helpers ---------------------------------------------------
__device__ __forceinline__ uint32_t smem_u32(const void* p) {
    uint32_t a;
    asm("{ .reg .u64 t; cvta.to.shared.u64 t, %1; cvt.u32.u64 %0, t; }" : "=r"(a) : "l"(p));
    return a;
}
#define SWZ(o) ((o) ^ (((o) >> 3) & 0x70))

__device__ __forceinline__ void cp16(uint32_t dst, const void* src) {
    asm volatile("cp.async.cg.shared.global [%0], [%1], 16;" :: "r"(dst), "l"(src));
}
#define CP_COMMIT() asm volatile("cp.async.commit_group;" ::: "memory")
#define CP_WAIT(n)  asm volatile("cp.async.wait_group %0;" :: "n"(n) : "memory")

#define LDSM4(r, addr) \
    asm volatile("ldmatrix.sync.aligned.m8n8.x4.shared.b16 {%0,%1,%2,%3}, [%4];" \
        : "=r"((r)[0]), "=r"((r)[1]), "=r"((r)[2]), "=r"((r)[3]) : "r"(addr))

#define MMA_F16(d, a, b0, b1) \
    asm volatile("mma.sync.aligned.m16n8k16.row.col.f32.f16.f16.f32 " \
        "{%0,%1,%2,%3}, {%4,%5,%6,%7}, {%8,%9}, {%0,%1,%2,%3};" \
        : "+f"((d)[0]), "+f"((d)[1]), "+f"((d)[2]), "+f"((d)[3]) \
        : "r"((a)[0]), "r"((a)[1]), "r"((a)[2]), "r"((a)[3]), "r"(b0), "r"(b1))

// ---------------------------------------------------------------------------
// HMMA fp16 GEMM (R6/R9 config): CTA tile BM=128, BN=128, BK=64; 8 warps
// (4m x 2n), warp tile 32x64. 3-stage cp.async pipeline (32KB/stage), occ 2.
// MODE 0 (KV): grid.x=8, W base -> [Wk|Wv]; slice0 = k (softmax, fp16 out),
//              slice1 = v (bias only, fp16 out).
// MODE 1 (Q):  grid.x=4, W = Wq; softmax, fp32 out.
// MODE 2 (P):  grid.x=4, W = Wp; bias only, fp32 out.
// ---------------------------------------------------------------------------
#define BKB   128            // bytes per smem row (64 fp16)
#define K0B   16384          // one 128x64 fp16 tile
#define STG   (2 * K0B)      // 32KB stage: A | B
#define NSTG  3
#define SMEM_GEMM (NSTG * STG)
#define K0STEPS 8

struct GArgs {
    const __half *A, *W;                      // W: base of (multi-)slice weights
    const float *b0, *b1;                     // bias per 512-col slice
    float* qf;                                // fp32 out (MODE 1/2)
    __half *kh, *vh;                          // fp16 outs (MODE 0)
};

__device__ __forceinline__ void load_k0(
    uint32_t sbase, int stage, int k0, int bm, int bnn, int tid,
    const __half* A, const __half* B)
{
    uint32_t s = sbase + stage * STG;
#pragma unroll
    for (int t = 0; t < 4; t++) {
        int idx = tid + t * 256;                  // 1024 x 16B per tile
        int row = idx >> 3, c = idx & 7;
        uint32_t off = SWZ((uint32_t)(row * BKB + c * 16));
        cp16(s + off,       A + (size_t)(bm + row) * 512 + k0 + c * 8);
        cp16(s + K0B + off, B + (size_t)(bnn + row) * 512 + k0 + c * 8);
    }
}

template <int MODE>
__global__ __launch_bounds__(256, 2) void mma_gemm_k(GArgs args)
{
    extern __shared__ char smem[];
    uint32_t sbase = smem_u32(smem);

    const int tid = threadIdx.x;
    const int lane = tid & 31;
    const int wid = tid >> 5;
    const int wm = (wid & 3) * 32;
    const int wn = (wid >> 2) * 64;
    const int bm = blockIdx.y * 128;
    const int bn = blockIdx.x * 128;
    const int slice = bn >> 9;
    const int bnn = bn & 511;

    const __half* W = args.W + (size_t)slice * NW1;
    const float* bias = (slice == 0) ? args.b0 : args.b1;
    const bool do_sm = (MODE == 1) || (MODE == 0 && slice == 0);

    float acc[2][8][4];
#pragma unroll
    for (int i = 0; i < 2; i++)
#pragma unroll
        for (int j = 0; j < 8; j++)
#pragma unroll
            for (int p = 0; p < 4; p++) acc[i][j][p] = 0.f;

    const int a_row = wm + (lane & 15);
    const int a_cb  = (lane >> 4) * 16;
    const int b_row = wn + (lane & 7) + ((lane >> 4) & 1) * 8;
    const int b_cb  = ((lane >> 3) & 1) * 16;

    load_k0(sbase, 0, 0, bm, bnn, tid, args.A, W);
    CP_COMMIT();
    load_k0(sbase, 1, 64, bm, bnn, tid, args.A, W);
    CP_COMMIT();

    for (int i = 0; i < K0STEPS; i++) {
        CP_WAIT(1);
        __syncthreads();
        if (i + 2 < K0STEPS)
            load_k0(sbase, (i + 2) % NSTG, (i + 2) * 64, bm, bnn, tid, args.A, W);
        CP_COMMIT();

        uint32_t sA = sbase + (i % NSTG) * STG;
        uint32_t sB = sA + K0B;
#pragma unroll
        for (int ks = 0; ks < 4; ks++) {
            uint32_t a[2][4], b[4][4];
#pragma unroll
            for (int mi = 0; mi < 2; mi++)
                LDSM4(a[mi], sA + SWZ((uint32_t)((a_row + mi * 16) * BKB + ks * 32 + a_cb)));
#pragma unroll
            for (int nb = 0; nb < 4; nb++)
                LDSM4(b[nb], sB + SWZ((uint32_t)((b_row + nb * 16) * BKB + ks * 32 + b_cb)));
#pragma unroll
            for (int mi = 0; mi < 2; mi++)
#pragma unroll
                for (int nb = 0; nb < 4; nb++) {
                    MMA_F16(acc[mi][nb * 2 + 0], a[mi], b[nb][0], b[nb][1]);
                    MMA_F16(acc[mi][nb * 2 + 1], a[mi], b[nb][2], b[nb][3]);
                }
        }
    }

    // ---- epilogue: bias, optional softmax, store --------------------------
#pragma unroll
    for (int nf = 0; nf < 8; nf++) {
        int col = bnn + wn + (lane & 3) * 2 + nf * 8;
        float bb0 = __ldg(bias + col);
        float bb1 = __ldg(bias + col + 1);
#pragma unroll
        for (int mi = 0; mi < 2; mi++) {
            acc[mi][nf][0] += bb0; acc[mi][nf][1] += bb1;
            acc[mi][nf][2] += bb0; acc[mi][nf][3] += bb1;
        }
    }

    if (do_sm) {
        // per-row softmax over the warp's 64 cols (row = lane quad)
#pragma unroll
        for (int mi = 0; mi < 2; mi++)
#pragma unroll
            for (int half = 0; half < 2; half++) {
                float m = -1e30f;
#pragma unroll
                for (int nf = 0; nf < 8; nf++)
                    m = fmaxf(m, fmaxf(acc[mi][nf][half * 2], acc[mi][nf][half * 2 + 1]));
                m = fmaxf(m, __shfl_xor_sync(0xffffffffu, m, 1));
                m = fmaxf(m, __shfl_xor_sync(0xffffffffu, m, 2));
                float s = 0.f;
#pragma unroll
                for (int nf = 0; nf < 8; nf++) {
                    float e0 = __expf(acc[mi][nf][half * 2] - m);
                    float e1 = __expf(acc[mi][nf][half * 2 + 1] - m);
                    acc[mi][nf][half * 2] = e0;
                    acc[mi][nf][half * 2 + 1] = e1;
                    s += e0 + e1;
                }
                s += __shfl_xor_sync(0xffffffffu, s, 1);
                s += __shfl_xor_sync(0xffffffffu, s, 2);
                float inv = 1.f / s;
#pragma unroll
                for (int nf = 0; nf < 8; nf++) {
                    acc[mi][nf][half * 2] *= inv;
                    acc[mi][nf][half * 2 + 1] *= inv;
                }
            }
    }

    const int r0 = bm + wm + (lane >> 2);
    const int c0 = bnn + wn + (lane & 3) * 2;

    if (MODE != 0) {
        float* out = args.qf;
#pragma unroll
        for (int nf = 0; nf < 8; nf++) {
            int col = c0 + nf * 8;
#pragma unroll
            for (int mi = 0; mi < 2; mi++) {
                int row = r0 + mi * 16;
                float2 v0 = {acc[mi][nf][0], acc[mi][nf][1]};
                float2 v1 = {acc[mi][nf][2], acc[mi][nf][3]};
                *(float2*)(out + (size_t)row * 512 + col) = v0;
                *(float2*)(out + (size_t)(row + 8) * 512 + col) = v1;
            }
        }
    } else {
        __half* out = (slice == 0) ? args.kh : args.vh;
#pragma unroll
        for (int nf = 0; nf < 8; nf++) {
            int col = c0 + nf * 8;
#pragma unroll
            for (int mi = 0; mi < 2; mi++) {
                int row = r0 + mi * 16;
                __half2 v0 = __floats2half2_rn(acc[mi][nf][0], acc[mi][nf][1]);
                __half2 v1 = __floats2half2_rn(acc[mi][nf][2], acc[mi][nf][3]);
                *(__half2*)(out + (size_t)row * 512 + col) = v0;
                *(__half2*)(out + (size_t)(row + 8) * 512 + col) = v1;
            }
        }
    }
}

// ---------------------------------------------------------------------------
// fused fp32 -> fp16 conversion: x + all four weights
// ---------------------------------------------------------------------------
__global__ __launch_bounds__(256) void conv_all_k(
    const float* __restrict__ x,
    const float* __restrict__ Wq, const float* __restrict__ Wk,
    const float* __restrict__ Wv, const float* __restrict__ Wp,
    __half* __restrict__ xf, __half* __restrict__ wf)
{
    int i = (blockIdx.x * 256 + threadIdx.x) * 4;
    const float* src;
    __half* dst;
    int o;
    if (i < NX) { src = x; dst = xf; o = i; }
    else {
        int j = i - NX;
        int w = j >> 18;                  // NW1 = 2^18
        o = j & (NW1 - 1);
        src = (w == 0) ? Wq : (w == 1) ? Wk : (w == 2) ? Wv : Wp;
        dst = wf + ((size_t)w << 18);
    }
    float4 v = *(const float4*)(src + o);
    *(__half2*)(dst + o)     = __floats2half2_rn(v.x, v.y);
    *(__half2*)(dst + o + 2) = __floats2half2_rn(v.z, v.w);
}

// ---------------------------------------------------------------------------
// context partials + k_sum partials; k,v fp16, T slice of 256 per block.
// ---------------------------------------------------------------------------
__global__ __launch_bounds__(256) void ctx_partial_k(
    const __half* __restrict__ K, const __half* __restrict__ V,
    float* __restrict__ ctxp, float* __restrict__ ksump)
{
    __shared__ float ks[32][68];
    __shared__ float vs[32][68];
    const int bh = blockIdx.x, b = bh >> 3, h = bh & 7;
    const int ts = blockIdx.y, tid = threadIdx.x;
    const int tx = tid & 15, ty = tid >> 4;
    const int col2 = (tid & 31) * 2;       // half2 column pair
    const int trow = tid >> 5;             // 8 t-rows per pass

    float acc[4][4];
#pragma unroll
    for (int i = 0; i < 4; i++)
#pragma unroll
        for (int j = 0; j < 4; j++) acc[i][j] = 0.f;
    float ksacc[4] = {0.f, 0.f, 0.f, 0.f};
    const int rowbase = b * 4096 + ts * 256;

    for (int tt = 0; tt < 256; tt += 32) {
#pragma unroll
        for (int p = 0; p < 4; p++) {
            int t = trow + p * 8;
            size_t g = (size_t)(rowbase + tt + t) * 512 + h * 64 + col2;
            float2 kf = __half22float2(*(const __half2*)(K + g));
            float2 vf = __half22float2(*(const __half2*)(V + g));
            ks[t][col2] = kf.x; ks[t][col2 + 1] = kf.y;
            vs[t][col2] = vf.x; vs[t][col2 + 1] = vf.y;
        }
        __syncthreads();
#pragma unroll
        for (int t = 0; t < 32; t++) {
            float4 af = *(const float4*)(&ks[t][ty * 4]);
            float4 bf = *(const float4*)(&vs[t][tx * 4]);
            float a[4] = {af.x, af.y, af.z, af.w};
            float bb[4] = {bf.x, bf.y, bf.z, bf.w};
#pragma unroll
            for (int i = 0; i < 4; i++)
#pragma unroll
                for (int j = 0; j < 4; j++) acc[i][j] += a[i] * bb[j];
            if (tx == 0)
#pragma unroll
                for (int i = 0; i < 4; i++) ksacc[i] += a[i];
        }
        __syncthreads();
    }
    float* cp = ctxp + (size_t)(ts * NBH + bh) * 4096;
#pragma unroll
    for (int i = 0; i < 4; i++)
#pragma unroll
        for (int j = 0; j < 4; j++)
            cp[(ty * 4 + i) * 64 + tx * 4 + j] = acc[i][j];
    if (tx == 0)
#pragma unroll
        for (int i = 0; i < 4; i++)
            ksump[(size_t)(ts * NBH + bh) * 64 + ty * 4 + i] = ksacc[i];
}

// combined reduce: ctx (NBH*4096) then ksum (NBH*64)
__global__ void reduce_all_k(const float* __restrict__ ctxp,
                             const float* __restrict__ ksump,
                             float* __restrict__ ctx, float* __restrict__ ksum)
{
    int i = blockIdx.x * blockDim.x + threadIdx.x;
    if (i < NBH * 4096) {
        float s = 0.f;
#pragma unroll
        for (int p = 0; p < TSPLIT; p++) s += ctxp[(size_t)p * NBH * 4096 + i];
        ctx[i] = s;
    } else {
        int j = i - NBH * 4096;
        if (j < NBH * 64) {
            float s = 0.f;
#pragma unroll
            for (int p = 0; p < TSPLIT; p++) s += ksump[(size_t)p * NBH * 64 + j];
            ksum[j] = s;
        }
    }
}

// ---------------------------------------------------------------------------
// out = (q @ ctx) * Dinv + q  -> fp16 o for final GEMM. q read fp32.
// ---------------------------------------------------------------------------
__global__ __launch_bounds__(256) void attn_out_k(
    const float* __restrict__ Q, const float* __restrict__ ctx,
    const float* __restrict__ ksum, __half* __restrict__ Oh)
{
    __shared__ float cs[64][64];
    __shared__ float qs[64][68];
    __shared__ float kss[64];
    const int bh = blockIdx.x, b = bh >> 3, h = bh & 7;
    const int tb = blockIdx.y, tid = threadIdx.x;

    const float* cg = ctx + (size_t)bh * 4096;
    for (int i = tid; i < 4096; i += 256) cs[i >> 6][i & 63] = cg[i];
    if (tid < 64) kss[tid] = ksum[bh * 64 + tid];

    const int rowbase = b * 4096 + tb * 64;
    const int col = tid & 63, rr = tid >> 6;
#pragma unroll
    for (int p = 0; p < 16; p++) {
        int r = rr + p * 4;
        qs[r][col] = Q[(size_t)(rowbase + r) * 512 + h * 64 + col];
    }
    __syncthreads();

    const int r = tid >> 2, e0 = (tid & 3) * 16;
    float acc[16];
#pragma unroll
    for (int j = 0; j < 16; j++) acc[j] = 0.f;
    float dv = 0.f;
#pragma unroll
    for (int d = 0; d < 64; d++) {
        float qv = qs[r][d];
        dv += qv * kss[d];
#pragma unroll
        for (int j = 0; j < 16; j++) acc[j] += qv * cs[d][e0 + j];
    }
    float Dinv = 1.f / dv;
    size_t base = (size_t)(rowbase + r) * 512 + h * 64 + e0;
#pragma unroll
    for (int j = 0; j < 16; j += 2) {
        float v0 = acc[j] * Dinv + qs[r][e0 + j];
        float v1 = acc[j + 1] * Dinv + qs[r][e0 + j + 1];
        *(__half2*)(Oh + base + j) = __floats2half2_rn(v0, v1);
    }
}

// ---------------------------------------------------------------------------
extern "C" void kernel_launch(void* const* d_in, const int* in_sizes, int n_in,
                              void* d_out, int out_size)
{
    const float* x  = (const float*)d_in[0];
    const float* Wq = (const float*)d_in[1];
    const float* bq = (const float*)d_in[2];
    const float* Wk = (const float*)d_in[3];
    const float* bk = (const float*)d_in[4];
    const float* Wv = (const float*)d_in[5];
    const float* bv = (const float*)d_in[6];
    const float* Wp = (const float*)d_in[7];
    const float* bp = (const float*)d_in[8];
    float* out = (float*)d_out;

    float *q, *ctx, *ksum, *ctxp, *ksump;
    __half *kh, *vh, *oh, *xf, *wf;
    cudaGetSymbolAddress((void**)&q, g_q);
    cudaGetSymbolAddress((void**)&kh, g_kh);
    cudaGetSymbolAddress((void**)&vh, g_vh);
    cudaGetSymbolAddress((void**)&oh, g_oh);
    cudaGetSymbolAddress((void**)&ctx, g_ctx);
    cudaGetSymbolAddress((void**)&ksum, g_ksum);
    cudaGetSymbolAddress((void**)&ctxp, g_ctxp);
    cudaGetSymbolAddress((void**)&ksump, g_ksump);
    cudaGetSymbolAddress((void**)&xf, g_xf);
    cudaGetSymbolAddress((void**)&wf, g_wf);

    // one-time host objects (no device work, no device allocation)
    static cudaStream_t s2 = nullptr;
    static cudaEvent_t evKV = nullptr, evQ = nullptr;
    if (s2 == nullptr) {
        cudaStreamCreateWithFlags(&s2, cudaStreamNonBlocking);
        cudaEventCreateWithFlags(&evKV, cudaEventDisableTiming);
        cudaEventCreateWithFlags(&evQ, cudaEventDisableTiming);
        cudaFuncSetAttribute(mma_gemm_k<0>, cudaFuncAttributeMaxDynamicSharedMemorySize, SMEM_GEMM);
        cudaFuncSetAttribute(mma_gemm_k<1>, cudaFuncAttributeMaxDynamicSharedMemorySize, SMEM_GEMM);
        cudaFuncSetAttribute(mma_gemm_k<2>, cudaFuncAttributeMaxDynamicSharedMemorySize, SMEM_GEMM);
    }

    // fp32 -> fp16 conversions (x + all weights, one launch)
    conv_all_k<<<(NX + 4 * NW1) / 4 / 256, 256>>>(x, Wq, Wk, Wv, Wp, xf, wf);

    // KV GEMM (slices: k -> softmax fp16, v -> bias fp16) on main stream
    GArgs akv{xf, wf + 1 * NW1, bk, bv, nullptr, kh, vh};
    mma_gemm_k<0><<<dim3(8, 128), 256, SMEM_GEMM>>>(akv);
    cudaEventRecord(evKV, 0);

    // Q GEMM on side stream, concurrent with the ctx chain below
    cudaStreamWaitEvent(s2, evKV, 0);
    GArgs aq{xf, wf, bq, bq, q, nullptr, nullptr};
    mma_gemm_k<1><<<dim3(4, 128), 256, SMEM_GEMM, s2>>>(aq);
    cudaEventRecord(evQ, s2);

    // ctx chain on main stream (overlaps with Q GEMM)
    ctx_partial_k<<<dim3(NBH, TSPLIT), 256>>>(kh, vh, ctxp, ksump);
    reduce_all_k<<<(NBH * 4096 + NBH * 64 + 255) / 256, 256>>>(ctxp, ksump, ctx, ksum);

    // join: attn needs q + ctx
    cudaStreamWaitEvent(0, evQ, 0);
    attn_out_k<<<dim3(NBH, 64), 256>>>(q, ctx, ksum, oh);

    // output projection (plain fp32 out)
    GArgs ap{oh, wf + 3 * NW1, bp, bp, out, nullptr, nullptr};
    mma_gemm_k<2><<<dim3(4, 128), 256, SMEM_GEMM>>>(ap);
}

// round 12
// speedup vs baseline: 1.9960x; 1.8292x over previous
#include <cuda_runtime.h>
#include <cuda_fp16.h>
#include <cstdint>

// Problem constants
#define M_TOT 16384          // B*T
#define NDIM  512
#define NBH   32             // B*H
#define TSPLIT 32
#define NX  (M_TOT * NDIM)   // 8388608
#define NW1 (NDIM * NDIM)    // 262144

// ---------------- scratch (__device__ globals; no allocation allowed) -------
__device__ __half g_qh[NX];                     // q post-softmax, fp16
__device__ __half g_kh[NX];                     // k post-softmax, fp16
__device__ __half g_vh[NX];                     // v, fp16
__device__ __half g_oh[NX];                     // attn out, fp16
__device__ float  g_ctxp[TSPLIT * NBH * 4160];  // transposed partials [e<=64][d]
__device__ __half g_ctxh[NBH * 80 * 72];        // ctx^T fp16 + ksum row 64
__device__ __half g_xf[NX];                     // x fp16
__device__ __half g_wf[4 * NW1];                // Wq|Wk|Wv|Wp fp16

// ---------------- helpers ---------------------------------------------------
__device__ __forceinline__ uint32_t smem_u32(const void* p) {
    uint32_t a;
    asm("{ .reg .u64 t; cvta.to.shared.u64 t, %1; cvt.u32.u64 %0, t; }" : "=r"(a) : "l"(p));
    return a;
}
#define SWZ(o) ((o) ^ (((o) >> 3) & 0x70))

__device__ __forceinline__ void cp16(uint32_t dst, const void* src) {
    asm volatile("cp.async.cg.shared.global [%0], [%1], 16;" :: "r"(dst), "l"(src));
}
#define CP_COMMIT() asm volatile("cp.async.commit_group;" ::: "memory")
#define CP_WAIT(n)  asm volatile("cp.async.wait_group %0;" :: "n"(n) : "memory")

#define LDSM4(r, addr) \
    asm volatile("ldmatrix.sync.aligned.m8n8.x4.shared.b16 {%0,%1,%2,%3}, [%4];" \
        : "=r"((r)[0]), "=r"((r)[1]), "=r"((r)[2]), "=r"((r)[3]) : "r"(addr))

#define MMA_F16(d, a, b0, b1) \
    asm volatile("mma.sync.aligned.m16n8k16.row.col.f32.f16.f16.f32 " \
        "{%0,%1,%2,%3}, {%4,%5,%6,%7}, {%8,%9}, {%0,%1,%2,%3};" \
        : "+f"((d)[0]), "+f"((d)[1]), "+f"((d)[2]), "+f"((d)[3]) \
        : "r"((a)[0]), "r"((a)[1]), "r"((a)[2]), "r"((a)[3]), "r"(b0), "r"(b1))

// ---------------------------------------------------------------------------
// HMMA fp16 GEMM: CTA tile BM=128, BN=128, BK=64; 8 warps (4m x 2n),
// warp tile 32x64. 3-stage cp.async pipeline, occ 2.
// MODE 0 (KV): grid.x=8, W base -> [Wk|Wv]; slice0 = k (softmax, fp16),
//              slice1 = v (bias only, fp16).
// MODE 1 (Q):  grid.x=4, W = Wq; softmax, fp16 out (args.kh).
// MODE 2 (P):  grid.x=4, W = Wp; bias only, fp32 out (args.qf).
// ---------------------------------------------------------------------------
#define BKB   128
#define K0B   16384
#define STG   (2 * K0B)
#define NSTG  3
#define SMEM_GEMM (NSTG * STG)
#define K0STEPS 8

struct GArgs {
    const __half *A, *W;
    const float *b0, *b1;
    float* qf;                                // fp32 out (MODE 2)
    __half *kh, *vh;                          // fp16 outs
};

__device__ __forceinline__ void load_k0(
    uint32_t sbase, int stage, int k0, int bm, int bnn, int tid,
    const __half* A, const __half* B)
{
    uint32_t s = sbase + stage * STG;
#pragma unroll
    for (int t = 0; t < 4; t++) {
        int idx = tid + t * 256;
        int row = idx >> 3, c = idx & 7;
        uint32_t off = SWZ((uint32_t)(row * BKB + c * 16));
        cp16(s + off,       A + (size_t)(bm + row) * 512 + k0 + c * 8);
        cp16(s + K0B + off, B + (size_t)(bnn + row) * 512 + k0 + c * 8);
    }
}

template <int MODE>
__global__ __launch_bounds__(256, 2) void mma_gemm_k(GArgs args)
{
    extern __shared__ char smem[];
    uint32_t sbase = smem_u32(smem);

    const int tid = threadIdx.x;
    const int lane = tid & 31;
    const int wid = tid >> 5;
    const int wm = (wid & 3) * 32;
    const int wn = (wid >> 2) * 64;
    const int bm = blockIdx.y * 128;
    const int bn = blockIdx.x * 128;
    const int slice = bn >> 9;
    const int bnn = bn & 511;

    const __half* W = args.W + (size_t)slice * NW1;
    const float* bias = (slice == 0) ? args.b0 : args.b1;
    const bool do_sm = (MODE == 1) || (MODE == 0 && slice == 0);

    float acc[2][8][4];
#pragma unroll
    for (int i = 0; i < 2; i++)
#pragma unroll
        for (int j = 0; j < 8; j++)
#pragma unroll
            for (int p = 0; p < 4; p++) acc[i][j][p] = 0.f;

    const int a_row = wm + (lane & 15);
    const int a_cb  = (lane >> 4) * 16;
    const int b_row = wn + (lane & 7) + ((lane >> 4) & 1) * 8;
    const int b_cb  = ((lane >> 3) & 1) * 16;

    load_k0(sbase, 0, 0, bm, bnn, tid, args.A, W);
    CP_COMMIT();
    load_k0(sbase, 1, 64, bm, bnn, tid, args.A, W);
    CP_COMMIT();

    for (int i = 0; i < K0STEPS; i++) {
        CP_WAIT(1);
        __syncthreads();
        if (i + 2 < K0STEPS)
            load_k0(sbase, (i + 2) % NSTG, (i + 2) * 64, bm, bnn, tid, args.A, W);
        CP_COMMIT();

        uint32_t sA = sbase + (i % NSTG) * STG;
        uint32_t sB = sA + K0B;
#pragma unroll
        for (int ks = 0; ks < 4; ks++) {
            uint32_t a[2][4], b[4][4];
#pragma unroll
            for (int mi = 0; mi < 2; mi++)
                LDSM4(a[mi], sA + SWZ((uint32_t)((a_row + mi * 16) * BKB + ks * 32 + a_cb)));
#pragma unroll
            for (int nb = 0; nb < 4; nb++)
                LDSM4(b[nb], sB + SWZ((uint32_t)((b_row + nb * 16) * BKB + ks * 32 + b_cb)));
#pragma unroll
            for (int mi = 0; mi < 2; mi++)
#pragma unroll
                for (int nb = 0; nb < 4; nb++) {
                    MMA_F16(acc[mi][nb * 2 + 0], a[mi], b[nb][0], b[nb][1]);
                    MMA_F16(acc[mi][nb * 2 + 1], a[mi], b[nb][2], b[nb][3]);
                }
        }
    }

    // ---- epilogue -----------------------------------------------------------
#pragma unroll
    for (int nf = 0; nf < 8; nf++) {
        int col = bnn + wn + (lane & 3) * 2 + nf * 8;
        float bb0 = __ldg(bias + col);
        float bb1 = __ldg(bias + col + 1);
#pragma unroll
        for (int mi = 0; mi < 2; mi++) {
            acc[mi][nf][0] += bb0; acc[mi][nf][1] += bb1;
            acc[mi][nf][2] += bb0; acc[mi][nf][3] += bb1;
        }
    }

    if (do_sm) {
#pragma unroll
        for (int mi = 0; mi < 2; mi++)
#pragma unroll
            for (int half = 0; half < 2; half++) {
                float m = -1e30f;
#pragma unroll
                for (int nf = 0; nf < 8; nf++)
                    m = fmaxf(m, fmaxf(acc[mi][nf][half * 2], acc[mi][nf][half * 2 + 1]));
                m = fmaxf(m, __shfl_xor_sync(0xffffffffu, m, 1));
                m = fmaxf(m, __shfl_xor_sync(0xffffffffu, m, 2));
                float s = 0.f;
#pragma unroll
                for (int nf = 0; nf < 8; nf++) {
                    float e0 = __expf(acc[mi][nf][half * 2] - m);
                    float e1 = __expf(acc[mi][nf][half * 2 + 1] - m);
                    acc[mi][nf][half * 2] = e0;
                    acc[mi][nf][half * 2 + 1] = e1;
                    s += e0 + e1;
                }
                s += __shfl_xor_sync(0xffffffffu, s, 1);
                s += __shfl_xor_sync(0xffffffffu, s, 2);
                float inv = 1.f / s;
#pragma unroll
                for (int nf = 0; nf < 8; nf++) {
                    acc[mi][nf][half * 2] *= inv;
                    acc[mi][nf][half * 2 + 1] *= inv;
                }
            }
    }

    const int r0 = bm + wm + (lane >> 2);
    const int c0 = bnn + wn + (lane & 3) * 2;

    if (MODE == 2) {
        float* out = args.qf;
#pragma unroll
        for (int nf = 0; nf < 8; nf++) {
            int col = c0 + nf * 8;
#pragma unroll
            for (int mi = 0; mi < 2; mi++) {
                int row = r0 + mi * 16;
                float2 v0 = {acc[mi][nf][0], acc[mi][nf][1]};
                float2 v1 = {acc[mi][nf][2], acc[mi][nf][3]};
                *(float2*)(out + (size_t)row * 512 + col) = v0;
                *(float2*)(out + (size_t)(row + 8) * 512 + col) = v1;
            }
        }
    } else {
        __half* out = (slice == 0) ? args.kh : args.vh;
#pragma unroll
        for (int nf = 0; nf < 8; nf++) {
            int col = c0 + nf * 8;
#pragma unroll
            for (int mi = 0; mi < 2; mi++) {
                int row = r0 + mi * 16;
                __half2 v0 = __floats2half2_rn(acc[mi][nf][0], acc[mi][nf][1]);
                __half2 v1 = __floats2half2_rn(acc[mi][nf][2], acc[mi][nf][3]);
                *(__half2*)(out + (size_t)row * 512 + col) = v0;
                *(__half2*)(out + (size_t)(row + 8) * 512 + col) = v1;
            }
        }
    }
}

// ---------------------------------------------------------------------------
// fused fp32 -> fp16 conversion: x + all four weights
// ---------------------------------------------------------------------------
__global__ __launch_bounds__(256) void conv_all_k(
    const float* __restrict__ x,
    const float* __restrict__ Wq, const float* __restrict__ Wk,
    const float* __restrict__ Wv, const float* __restrict__ Wp,
    __half* __restrict__ xf, __half* __restrict__ wf)
{
    int i = (blockIdx.x * 256 + threadIdx.x) * 4;
    const float* src;
    __half* dst;
    int o;
    if (i < NX) { src = x; dst = xf; o = i; }
    else {
        int j = i - NX;
        int w = j >> 18;
        o = j & (NW1 - 1);
        src = (w == 0) ? Wq : (w == 1) ? Wk : (w == 2) ? Wv : Wp;
        dst = wf + ((size_t)w << 18);
    }
    float4 v = *(const float4*)(src + o);
    *(__half2*)(dst + o)     = __floats2half2_rn(v.x, v.y);
    *(__half2*)(dst + o + 2) = __floats2half2_rn(v.z, v.w);
}

// ---------------------------------------------------------------------------
// ctx partials via HMMA: D[d][e] = sum_t k[t,d] v[t,e] over 128-t slice.
// k,v transposed into smem (k_s[d][t], v_s[e][t], 144B rows, conflict-free
// for LDSM). v_s row e=64 = ones -> ksum lands in acc col 64.
// Output: ctxpT[ts][bh][e<=64][d] fp32 (row 64 = ksum), written transposed
// via an smem staging pass for coalescing.
// grid (NBH, TSPLIT), 128 threads (4 warps, one m16 block each, n=80).
// ---------------------------------------------------------------------------
__global__ __launch_bounds__(128) void ctx_partial_k(
    const __half* __restrict__ K, const __half* __restrict__ V,
    float* __restrict__ ctxpT)
{
    __shared__ __align__(16) char sm[20736];
    __half* k_s = (__half*)sm;              // [64][72]
    __half* v_s = k_s + 64 * 72;            // [80][72]
    float* sm_acc = (float*)sm;             // [64][81] (reused after MMA)

    const int bh = blockIdx.x, b = bh >> 3, h = bh & 7;
    const int ts = blockIdx.y, tid = threadIdx.x;
    const int wid = tid >> 5, lane = tid & 31;
    const uint32_t k_su = smem_u32(k_s), v_su = smem_u32(v_s);
    const int rowbase = b * 4096 + ts * 128;

    // init v_s rows 64..79 (row 64 = ones, rest zero); staging never touches them
    const __half one = __float2half(1.f), zero = __float2half(0.f);
    for (int i = tid; i < 16 * 72; i += 128) {
        int r = 64 + i / 72, c = i % 72;
        v_s[r * 72 + c] = (r == 64) ? one : zero;
    }

    float acc[10][4];
#pragma unroll
    for (int j = 0; j < 10; j++)
#pragma unroll
        for (int p = 0; p < 4; p++) acc[j][p] = 0.f;

    const int a_row = wid * 16 + (lane & 15);
    const int a_cb  = (lane >> 4) * 16;
    const int b_rb  = (lane & 7) + ((lane >> 4) & 1) * 8;
    const int b_cb  = ((lane >> 3) & 1) * 16;

    for (int ch = 0; ch < 2; ch++) {
        __syncthreads();
        // stage transposed: k_s[d][t] = K[t][d], v_s[e][t] = V[t][e]
        for (int i = tid; i < 512; i += 128) {
            int t = i & 63, c = i >> 6;
            size_t g = (size_t)(rowbase + ch * 64 + t) * 512 + h * 64 + c * 8;
            uint4 kq = *(const uint4*)(K + g);
            uint4 vq = *(const uint4*)(V + g);
            const __half* kp = (const __half*)&kq;
            const __half* vp = (const __half*)&vq;
#pragma unroll
            for (int j = 0; j < 8; j++) {
                k_s[(c * 8 + j) * 72 + t] = kp[j];
                v_s[(c * 8 + j) * 72 + t] = vp[j];
            }
        }
        __syncthreads();
#pragma unroll
        for (int ks = 0; ks < 4; ks++) {
            uint32_t a[4], bf[5][4];
            LDSM4(a, k_su + (uint32_t)(a_row * 144 + ks * 32 + a_cb));
#pragma unroll
            for (int nb = 0; nb < 5; nb++)
                LDSM4(bf[nb], v_su + (uint32_t)((nb * 16 + b_rb) * 144 + ks * 32 + b_cb));
#pragma unroll
            for (int nb = 0; nb < 5; nb++) {
                MMA_F16(acc[nb * 2 + 0], a, bf[nb][0], bf[nb][1]);
                MMA_F16(acc[nb * 2 + 1], a, bf[nb][2], bf[nb][3]);
            }
        }
    }
    __syncthreads();

    // acc -> sm_acc[64][81] (cols 0..64 useful; col 64 = ksum)
    {
        const int r = lane >> 2, c0 = (lane & 3) * 2;
#pragma unroll
        for (int j = 0; j < 10; j++) {
            int col = j * 8 + c0;
            if (col < 65) {
                sm_acc[(wid * 16 + r) * 81 + col]     = acc[j][0];
                sm_acc[(wid * 16 + r + 8) * 81 + col] = acc[j][2];
                if (col + 1 < 65) {
                    sm_acc[(wid * 16 + r) * 81 + col + 1]     = acc[j][1];
                    sm_acc[(wid * 16 + r + 8) * 81 + col + 1] = acc[j][3];
                }
            }
        }
    }
    __syncthreads();

    // write ctxpT rows e=0..64, coalesced float4
    float* outp = ctxpT + (size_t)(ts * NBH + bh) * 4160;
    for (int i = tid; i < 65 * 16; i += 128) {
        int e = i >> 4, dq = (i & 15) * 4;
        float4 o;
        o.x = sm_acc[(dq + 0) * 81 + e];
        o.y = sm_acc[(dq + 1) * 81 + e];
        o.z = sm_acc[(dq + 2) * 81 + e];
        o.w = sm_acc[(dq + 3) * 81 + e];
        *(float4*)(outp + e * 64 + dq) = o;
    }
}

// ---------------------------------------------------------------------------
// reduce partials -> ctxh fp16 [bh][80 e-rows][72 d-cols]; row 64 = ksum,
// rows 65..79 and cols 64..71 zero.
// ---------------------------------------------------------------------------
__global__ void reduce_ctxh_k(const float* __restrict__ ctxpT,
                              __half* __restrict__ ctxh)
{
    int i = blockIdx.x * 256 + threadIdx.x;
    if (i >= NBH * 5760) return;
    int bh = i / 5760, rem = i % 5760, e = rem / 72, d = rem % 72;
    float s = 0.f;
    if (d < 64 && e <= 64) {
#pragma unroll
        for (int p = 0; p < TSPLIT; p++)
            s += ctxpT[(size_t)(p * NBH + bh) * 4160 + e * 64 + d];
    }
    ctxh[i] = __float2half(s);
}

// ---------------------------------------------------------------------------
// attn out via HMMA: o[t][e] = (q@ctx)[t][e] * Dinv + q[t][e], fp16.
// A = q (SW128 smem, normal ldmatrix), B = ctxh^T rows [e][d] (144B stride);
// acc col 64 = q . ksum = 1/Dinv (ksum folded as ctx row 64).
// grid (NBH, 16), 256 threads (8 warps x m32, n=80).
// ---------------------------------------------------------------------------
__global__ __launch_bounds__(256) void attn_out_k(
    const __half* __restrict__ Qh, const __half* __restrict__ ctxh,
    __half* __restrict__ Oh)
{
    __shared__ __align__(16) __half qs[256 * 64];    // SW128 rows
    __shared__ __align__(16) __half ctx_s[80 * 72];
    const int bh = blockIdx.x, b = bh >> 3, h = bh & 7;
    const int tb = blockIdx.y, tid = threadIdx.x;
    const int wid = tid >> 5, lane = tid & 31;
    const uint32_t qsu = smem_u32(qs), csu = smem_u32(ctx_s);
    const int rowbase = b * 4096 + tb * 256;

    for (int i = tid; i < 2048; i += 256) {
        int row = i >> 3, c = i & 7;
        cp16(qsu + SWZ((uint32_t)(row * 128 + c * 16)),
             Qh + (size_t)(rowbase + row) * 512 + h * 64 + c * 8);
    }
    for (int i = tid; i < 720; i += 256)
        cp16(csu + i * 16, ctxh + (size_t)bh * 5760 + i * 8);
    CP_COMMIT();
    CP_WAIT(0);
    __syncthreads();

    float acc[2][10][4];
#pragma unroll
    for (int mi = 0; mi < 2; mi++)
#pragma unroll
        for (int j = 0; j < 10; j++)
#pragma unroll
            for (int p = 0; p < 4; p++) acc[mi][j][p] = 0.f;

    const int a_row = wid * 32 + (lane & 15);
    const int a_cb  = (lane >> 4) * 16;
    const int b_rb  = (lane & 7) + ((lane >> 4) & 1) * 8;
    const int b_cb  = ((lane >> 3) & 1) * 16;

#pragma unroll
    for (int ks = 0; ks < 4; ks++) {
        uint32_t a[2][4], bf[5][4];
#pragma unroll
        for (int mi = 0; mi < 2; mi++)
            LDSM4(a[mi], qsu + SWZ((uint32_t)((a_row + mi * 16) * 128 + ks * 32 + a_cb)));
#pragma unroll
        for (int nb = 0; nb < 5; nb++)
            LDSM4(bf[nb], csu + (uint32_t)((nb * 16 + b_rb) * 144 + ks * 32 + b_cb));
#pragma unroll
        for (int mi = 0; mi < 2; mi++)
#pragma unroll
            for (int nb = 0; nb < 5; nb++) {
                MMA_F16(acc[mi][nb * 2 + 0], a[mi], bf[nb][0], bf[nb][1]);
                MMA_F16(acc[mi][nb * 2 + 1], a[mi], bf[nb][2], bf[nb][3]);
            }
    }

    const int r0 = lane >> 2, c0 = (lane & 3) * 2;
#pragma unroll
    for (int mi = 0; mi < 2; mi++) {
        int rb = wid * 32 + mi * 16;
        float dv0 = __shfl_sync(0xffffffffu, acc[mi][8][0], lane & ~3);
        float dv1 = __shfl_sync(0xffffffffu, acc[mi][8][2], lane & ~3);
        float Di0 = 1.f / dv0, Di1 = 1.f / dv1;
#pragma unroll
        for (int nf = 0; nf < 8; nf++) {
            int col = nf * 8 + c0;
            __half2 q0 = *(__half2*)((char*)qs + SWZ((uint32_t)((rb + r0) * 128 + col * 2)));
            __half2 q1 = *(__half2*)((char*)qs + SWZ((uint32_t)((rb + r0 + 8) * 128 + col * 2)));
            float2 qf0 = __half22float2(q0), qf1 = __half22float2(q1);
            __half2 o0 = __floats2half2_rn(acc[mi][nf][0] * Di0 + qf0.x,
                                           acc[mi][nf][1] * Di0 + qf0.y);
            __half2 o1 = __floats2half2_rn(acc[mi][nf][2] * Di1 + qf1.x,
                                           acc[mi][nf][3] * Di1 + qf1.y);
            *(__half2*)(Oh + (size_t)(rowbase + rb + r0) * 512 + h * 64 + col) = o0;
            *(__half2*)(Oh + (size_t)(rowbase + rb + r0 + 8) * 512 + h * 64 + col) = o1;
        }
    }
}

// ---------------------------------------------------------------------------
extern "C" void kernel_launch(void* const* d_in, const int* in_sizes, int n_in,
                              void* d_out, int out_size)
{
    const float* x  = (const float*)d_in[0];
    const float* Wq = (const float*)d_in[1];
    const float* bq = (const float*)d_in[2];
    const float* Wk = (const float*)d_in[3];
    const float* bk = (const float*)d_in[4];
    const float* Wv = (const float*)d_in[5];
    const float* bv = (const float*)d_in[6];
    const float* Wp = (const float*)d_in[7];
    const float* bp = (const float*)d_in[8];
    float* out = (float*)d_out;

    float *ctxpT;
    __half *qh, *kh, *vh, *oh, *xf, *wf, *ctxh;
    cudaGetSymbolAddress((void**)&qh, g_qh);
    cudaGetSymbolAddress((void**)&kh, g_kh);
    cudaGetSymbolAddress((void**)&vh, g_vh);
    cudaGetSymbolAddress((void**)&oh, g_oh);
    cudaGetSymbolAddress((void**)&ctxpT, g_ctxp);
    cudaGetSymbolAddress((void**)&ctxh, g_ctxh);
    cudaGetSymbolAddress((void**)&xf, g_xf);
    cudaGetSymbolAddress((void**)&wf, g_wf);

    static cudaStream_t s2 = nullptr;
    static cudaEvent_t evKV = nullptr, evQ = nullptr;
    if (s2 == nullptr) {
        cudaStreamCreateWithFlags(&s2, cudaStreamNonBlocking);
        cudaEventCreateWithFlags(&evKV, cudaEventDisableTiming);
        cudaEventCreateWithFlags(&evQ, cudaEventDisableTiming);
        cudaFuncSetAttribute(mma_gemm_k<0>, cudaFuncAttributeMaxDynamicSharedMemorySize, SMEM_GEMM);
        cudaFuncSetAttribute(mma_gemm_k<1>, cudaFuncAttributeMaxDynamicSharedMemorySize, SMEM_GEMM);
        cudaFuncSetAttribute(mma_gemm_k<2>, cudaFuncAttributeMaxDynamicSharedMemorySize, SMEM_GEMM);
    }

    // fp32 -> fp16 conversions
    conv_all_k<<<(NX + 4 * NW1) / 4 / 256, 256>>>(x, Wq, Wk, Wv, Wp, xf, wf);

    // KV GEMM on main stream
    GArgs akv{xf, wf + 1 * NW1, bk, bv, nullptr, kh, vh};
    mma_gemm_k<0><<<dim3(8, 128), 256, SMEM_GEMM>>>(akv);
    cudaEventRecord(evKV, 0);

    // Q GEMM (fp16 out) on side stream, concurrent with ctx chain
    cudaStreamWaitEvent(s2, evKV, 0);
    GArgs aq{xf, wf, bq, bq, nullptr, qh, nullptr};
    mma_gemm_k<1><<<dim3(4, 128), 256, SMEM_GEMM, s2>>>(aq);
    cudaEventRecord(evQ, s2);

    // ctx chain (HMMA) on main stream
    ctx_partial_k<<<dim3(NBH, TSPLIT), 128>>>(kh, vh, ctxpT);
    reduce_ctxh_k<<<(NBH * 5760 + 255) / 256, 256>>>(ctxpT, ctxh);

    // join: attn needs q + ctxh
    cudaStreamWaitEvent(0, evQ, 0);
    attn_out_k<<<dim3(NBH, 16), 256>>>(qh, ctxh, oh);

    // output projection
    GArgs ap{oh, wf + 3 * NW1, bp, bp, out, nullptr, nullptr};
    mma_gemm_k<2><<<dim3(4, 128), 256, SMEM_GEMM>>>(ap);
}